// round 15
// baseline (speedup 1.0000x reference)
#include <cuda_runtime.h>
#include <cuda_bf16.h>
#include <math.h>
#include <stdint.h>

#define FH 50
#define FW 50
#define NPOS 2500
#define CIN 256
#define CMID 512
#define KDIM 2304          // 256*9 (reordered: (ky*3+kx)*256+ci)
#define APER 9
#define NANCH 22500
#define NPRE 6000
#define NPOST 300
#define NSORT2 8192
#define NWORDS 94
#define NMS_T 0.7f
#define MINSZ 16.0f

#define BM 64
#define BN 64
#define NKT 36             // 36 k-tiles of 64: (ky,kx) = kt/4, ci0 = (kt%4)*64
#define PPOS 2704          // 52*52 padded positions
#define PTOT 2832          // + zero tail region

// smem layout (conv): DOUBLE-BUFFERED: per buf 3 A tiles (8KB) + 3 B tiles (8KB) = 48KB
#define BUFSZ    49152
#define OFF_B    (3*8192)
#define SMEM_CONV (2*BUFSZ)          // 98304

// ---------------- device scratch (zero-initialized at module load) ----------------
__device__ __align__(16) __nv_bfloat16 g_wh[CMID * KDIM];
__device__ __align__(16) __nv_bfloat16 g_wm[CMID * KDIM];
__device__ __align__(16) __nv_bfloat16 g_wl[CMID * KDIM];
__device__ __align__(16) __nv_bfloat16 g_xh[2 * PTOT * 256];
__device__ __align__(16) __nv_bfloat16 g_xm[2 * PTOT * 256];
__device__ __align__(16) __nv_bfloat16 g_xl[2 * PTOT * 256];
__device__ float g_h[2 * CMID * NPOS];
__device__ __align__(16) float g_boxes[2 * NANCH * 4];
__device__ float g_scores[2 * NANCH];
__device__ unsigned long long g_keys[2 * NANCH];
__device__ int g_hist[3][2][65536];
__device__ int g_T[3][2];
__device__ int g_G[3][2];
__device__ int g_cnt[2];
__device__ unsigned long long g_cand[2][NPRE];
__device__ __align__(16) float g_boxes6k[2 * NPRE * 4];
__device__ float g_scores6k[2 * NPRE];

// ---------------- helpers ----------------
__device__ __forceinline__ uint32_t smem_u32(const void* p) {
    uint32_t a;
    asm("{ .reg .u64 t; cvta.to.shared.u64 t, %1; cvt.u32.u64 %0, t; }" : "=r"(a) : "l"(p));
    return a;
}
__device__ __forceinline__ void cp16(uint32_t saddr, const void* gptr) {
    asm volatile("cp.async.cg.shared.global [%0], [%1], 16;" :: "r"(saddr), "l"(gptr));
}
__device__ __forceinline__ void ldsm_x4(uint32_t& r0, uint32_t& r1, uint32_t& r2, uint32_t& r3,
                                        uint32_t addr) {
    asm volatile("ldmatrix.sync.aligned.m8n8.x4.shared.b16 {%0,%1,%2,%3}, [%4];"
                 : "=r"(r0), "=r"(r1), "=r"(r2), "=r"(r3) : "r"(addr));
}
__device__ __forceinline__ void mma16816(float* d, const uint32_t* a, uint32_t b0, uint32_t b1) {
    asm volatile(
        "mma.sync.aligned.m16n8k16.row.col.f32.bf16.bf16.f32 "
        "{%0,%1,%2,%3}, {%4,%5,%6,%7}, {%8,%9}, {%0,%1,%2,%3};"
        : "+f"(d[0]), "+f"(d[1]), "+f"(d[2]), "+f"(d[3])
        : "r"(a[0]), "r"(a[1]), "r"(a[2]), "r"(a[3]), "r"(b0), "r"(b1));
}
__device__ __forceinline__ void mma16816_z(float* d, const uint32_t* a, uint32_t b0, uint32_t b1) {
    asm volatile(
        "mma.sync.aligned.m16n8k16.row.col.f32.bf16.bf16.f32 "
        "{%0,%1,%2,%3}, {%4,%5,%6,%7}, {%8,%9}, {%10,%11,%12,%13};"
        : "=f"(d[0]), "=f"(d[1]), "=f"(d[2]), "=f"(d[3])
        : "r"(a[0]), "r"(a[1]), "r"(a[2]), "r"(a[3]), "r"(b0), "r"(b1),
          "f"(0.f), "f"(0.f), "f"(0.f), "f"(0.f));
}

// ---------------- zero hist/counters ----------------
__global__ __launch_bounds__(1024) void zero_kernel() {
    const int idx = blockIdx.x * 1024 + threadIdx.x;
    if (idx < 3 * 2 * 65536) ((int*)g_hist)[idx] = 0;
    if (idx < 2) g_cnt[idx] = 0;
}

// ---------------- split + reorder weights: k' = (ky*3+kx)*256 + ci ----------------
__global__ __launch_bounds__(256) void split_w_kernel(const float* __restrict__ w) {
    const int idx = blockIdx.x * 256 + threadIdx.x;
    if (idx >= CMID * KDIM) return;
    const int co = idx / KDIM;
    const int k  = idx - co * KDIM;
    const int ci = k / 9;
    const int rr = k - ci * 9;
    const int dst = co * KDIM + rr * 256 + ci;
    const float v = w[idx];
    const __nv_bfloat16 h = __float2bfloat16(v);
    const float fh = __bfloat162float(h);
    const __nv_bfloat16 m = __float2bfloat16(v - fh);
    const float fm = __bfloat162float(m);
    const __nv_bfloat16 l = __float2bfloat16(v - fh - fm);
    g_wh[dst] = h; g_wm[dst] = m; g_wl[dst] = l;
}

// ---------------- split x into channel-last padded bf16 hi/mid/lo ----------------
__global__ __launch_bounds__(256) void split_x_kernel(const float* __restrict__ x) {
    const int idx = blockIdx.x * 256 + threadIdx.x;
    if (idx >= 2 * PPOS * 256) return;
    const int b   = idx / (PPOS * 256);
    const int rem = idx - b * (PPOS * 256);
    const int pos = rem >> 8;
    const int ci  = rem & 255;
    const int py = pos / 52, px = pos - py * 52;
    const int iy = py - 1,  ix = px - 1;
    float v = 0.f;
    if (iy >= 0 && iy < FH && ix >= 0 && ix < FW)
        v = x[(((size_t)b * CIN + ci) * FH + iy) * FW + ix];
    const __nv_bfloat16 h = __float2bfloat16(v);
    const float fh = __bfloat162float(h);
    const __nv_bfloat16 m = __float2bfloat16(v - fh);
    const float fm = __bfloat162float(m);
    const __nv_bfloat16 l = __float2bfloat16(v - fh - fm);
    const size_t dst = ((size_t)b * PTOT + pos) * 256 + ci;
    g_xh[dst] = h; g_xm[dst] = m; g_xl[dst] = l;
}

// ---------------- conv 3x3 via mma.sync bf16 (R14-proven) ----------------
__global__ __launch_bounds__(256) void conv_mma_kernel(const float* __restrict__ bias) {
    extern __shared__ __align__(128) char smem[];
    const uint32_t sbase = smem_u32(smem);
    const int t    = threadIdx.x;
    const int wid  = t >> 5, lane = t & 31;
    const int wm   = wid & 1;
    const int wn   = wid >> 1;
    const int n0   = blockIdx.x * BN;
    const int co0  = blockIdx.y * BM;
    const int b    = blockIdx.z;

    const __nv_bfloat16* Asrc[3] = {g_wh, g_wm, g_wl};
    const __nv_bfloat16* Xsrc[3] = {g_xh, g_xm, g_xl};

    float acc[2][2][4];
#pragma unroll
    for (int i = 0; i < 2; i++)
#pragma unroll
        for (int j = 0; j < 2; j++)
#pragma unroll
            for (int q = 0; q < 4; q++) acc[i][j][q] = 0.f;

    const int arow_l  = lane & 15;
    const int ahalf   = lane >> 4;
    const int bq = lane >> 3, br = lane & 7;
    const int brow_l = wn * 16 + (bq >> 1) * 8 + br;
    const int bhalf  = bq & 1;

    auto stage = [&](int kt, int buf) {
        const int k0 = kt * 64;
        const int r   = kt >> 2;
        const int ky  = r / 3, kx = r - ky * 3;
        const int ci0 = (kt & 3) * 64;
        const int kofs = ky * 52 + kx;
        const uint32_t base = sbase + buf * BUFSZ;
#pragma unroll
        for (int s = 0; s < 6; s++) {
            const int i = t + s * 256;
            const int tile = i / 512, g = i - tile * 512;
            const int row = g >> 3, c = g & 7;
            const uint32_t saddr = base + tile * 8192 + row * 128 + ((c * 16) ^ ((row & 7) << 4));
            cp16(saddr, Asrc[tile] + (size_t)(co0 + row) * KDIM + k0 + c * 8);
        }
#pragma unroll
        for (int s = 0; s < 6; s++) {
            const int i = t + s * 256;
            const int tile = i / 512, g = i - tile * 512;
            const int row = g >> 3, c = g & 7;
            const int n = n0 + row;
            int pos;
            if (n < NPOS) { const int y = n / FW; pos = y * 52 + (n - y * FW) + kofs; }
            else pos = PPOS;
            const uint32_t saddr = base + OFF_B + tile * 8192 + row * 128 + ((c * 16) ^ ((row & 7) << 4));
            cp16(saddr, Xsrc[tile] + ((size_t)b * PTOT + pos) * 256 + ci0 + c * 8);
        }
        asm volatile("cp.async.commit_group;" ::: "memory");
    };

    stage(0, 0);
    asm volatile("cp.async.wait_group 0;" ::: "memory");
    __syncthreads();

    for (int kt = 0; kt < NKT; kt++) {
        const int p = kt & 1;
        const bool more = (kt + 1) < NKT;
        if (more) stage(kt + 1, 1 - p);

        const uint32_t base = sbase + p * BUFSZ;
#pragma unroll
        for (int ks = 0; ks < 4; ks++) {
            uint32_t afr[3][2][4];
            uint32_t bfr[3][4];
#pragma unroll
            for (int tile = 0; tile < 3; tile++) {
#pragma unroll
                for (int mf = 0; mf < 2; mf++) {
                    const int row = wm * 32 + mf * 16 + arow_l;
                    const int cb  = ks * 32 + ahalf * 16;
                    const uint32_t addr = base + tile * 8192 + row * 128 +
                                          (cb ^ ((row & 7) << 4));
                    ldsm_x4(afr[tile][mf][0], afr[tile][mf][1], afr[tile][mf][2], afr[tile][mf][3], addr);
                }
                {
                    const int cb = ks * 32 + bhalf * 16;
                    const uint32_t addr = base + OFF_B + tile * 8192 + brow_l * 128 +
                                          (cb ^ ((brow_l & 7) << 4));
                    ldsm_x4(bfr[tile][0], bfr[tile][1], bfr[tile][2], bfr[tile][3], addr);
                }
            }
#pragma unroll
            for (int mf = 0; mf < 2; mf++) {
#pragma unroll
                for (int nf = 0; nf < 2; nf++) {
                    const uint32_t b0h = bfr[0][nf * 2], b1h = bfr[0][nf * 2 + 1];
                    const uint32_t b0m = bfr[1][nf * 2], b1m = bfr[1][nf * 2 + 1];
                    const uint32_t b0l = bfr[2][nf * 2], b1l = bfr[2][nf * 2 + 1];
                    float tmp[4];
                    mma16816_z(tmp, afr[0][mf], b0h, b1h);   // hh
                    mma16816 (tmp, afr[0][mf], b0m, b1m);    // hm
                    mma16816 (tmp, afr[1][mf], b0h, b1h);    // mh
                    mma16816 (tmp, afr[0][mf], b0l, b1l);    // hl
                    mma16816 (tmp, afr[2][mf], b0h, b1h);    // lh
                    mma16816 (tmp, afr[1][mf], b0m, b1m);    // mm
#pragma unroll
                    for (int q = 0; q < 4; q++) acc[mf][nf][q] += tmp[q];
                }
            }
        }
        if (more) {
            asm volatile("cp.async.wait_group 0;" ::: "memory");
            __syncthreads();
        }
    }

#pragma unroll
    for (int mf = 0; mf < 2; mf++) {
#pragma unroll
        for (int nf = 0; nf < 2; nf++) {
#pragma unroll
            for (int q = 0; q < 4; q++) {
                const int co = co0 + wm * 32 + mf * 16 + (lane >> 2) + (q >= 2 ? 8 : 0);
                const int n  = n0 + wn * 16 + nf * 8 + (lane & 3) * 2 + (q & 1);
                if (n < NPOS) {
                    float v = acc[mf][nf][q] + bias[co];
                    g_h[((size_t)(b * CMID + co)) * NPOS + n] = v > 0.f ? v : 0.f;
                }
            }
        }
    }
}

// ---------------- heads (R1-proven) ----------------
__device__ __forceinline__ float to_dim(const int* p) {
    int v = *p;
    if (v > 0 && v < 100000) return (float)v;
    return __int_as_float(v);
}

__global__ __launch_bounds__(256) void heads_kernel(
    const float* __restrict__ ow, const float* __restrict__ ob,
    const float* __restrict__ lw, const float* __restrict__ lb,
    const float* __restrict__ anchors, const int* ihp, const int* iwp)
{
    const int b  = blockIdx.y;
    const int n0 = blockIdx.x * 16;
    const int t  = threadIdx.x;

    __shared__ float hs[CMID][17];
    __shared__ float outs[54][16];

    for (int idx = t; idx < CMID * 16; idx += 256) {
        const int c = idx >> 4, i = idx & 15;
        const int n = n0 + i;
        hs[c][i] = (n < NPOS) ? g_h[((size_t)(b * CMID + c)) * NPOS + n] : 0.f;
    }
    __syncthreads();

    {
        const int i = t & 15, g = t >> 4;
        float acc[4] = {0.f, 0.f, 0.f, 0.f};
        const float* wp[4];
        float bs[4];
#pragma unroll
        for (int s = 0; s < 4; s++) {
            const int oc = g + s * 16;
            if (oc < 18)       { wp[s] = ow + oc * CMID;        bs[s] = ob[oc]; }
            else if (oc < 54)  { wp[s] = lw + (oc - 18) * CMID; bs[s] = lb[oc - 18]; }
            else               { wp[s] = ow;                    bs[s] = 0.f; }
        }
#pragma unroll 4
        for (int c = 0; c < CMID; c++) {
            const float v = hs[c][i];
            acc[0] += wp[0][c] * v;
            acc[1] += wp[1][c] * v;
            acc[2] += wp[2][c] * v;
            acc[3] += wp[3][c] * v;
        }
#pragma unroll
        for (int s = 0; s < 4; s++) {
            const int oc = g + s * 16;
            if (oc < 54) outs[oc][i] = acc[s] + bs[s];
        }
    }
    __syncthreads();

    if (t < 144) {
        const int i = t & 15, a = t >> 4;
        const int n = n0 + i;
        if (n < NPOS) {
            const float imgw = to_dim(iwp), imgh = to_dim(ihp);
            const int m = n * APER + a;
            const float o0 = outs[2 * a][i], o1 = outs[2 * a + 1][i];
            const float mx = fmaxf(o0, o1);
            const float e0 = expf(o0 - mx), e1 = expf(o1 - mx);
            const float sc = e1 / (e0 + e1);

            const float l0 = outs[18 + 4 * a + 0][i];
            const float l1 = outs[18 + 4 * a + 1][i];
            const float l2 = outs[18 + 4 * a + 2][i];
            const float l3 = outs[18 + 4 * a + 3][i];

            const float a0 = anchors[m * 4 + 0], a1 = anchors[m * 4 + 1];
            const float a2 = anchors[m * 4 + 2], a3 = anchors[m * 4 + 3];
            const float aw = a2 - a0, ah = a3 - a1;
            const float acx = a0 + 0.5f * aw, acy = a1 + 0.5f * ah;
            const float cx = acx + l0 * aw, cy = acy + l1 * ah;
            const float wd = aw * expf(l2), hh = ah * expf(l3);
            float x1 = fminf(fmaxf(cx - 0.5f * wd, 0.f), imgw);
            float y1 = fminf(fmaxf(cy - 0.5f * hh, 0.f), imgh);
            float x2 = fminf(fmaxf(cx + 0.5f * wd, 0.f), imgw);
            float y2 = fminf(fmaxf(cy + 0.5f * hh, 0.f), imgh);

            const bool valid = (x2 - x1 >= MINSZ) && (y2 - y1 >= MINSZ);
            const float s2 = valid ? sc : -1.f;

            float* bp = g_boxes + ((size_t)(b * NANCH + m)) * 4;
            bp[0] = x1; bp[1] = y1; bp[2] = x2; bp[3] = y2;
            g_scores[b * NANCH + m] = s2;

            const unsigned sb = __float_as_uint(s2);
            const unsigned mono = (sb & 0x80000000u) ? ~sb : (sb | 0x80000000u);
            g_keys[b * NANCH + m] =
                ((unsigned long long)mono << 32) |
                (unsigned long long)(0xFFFFFFFFu - (unsigned)m);
        }
    }
}

// ---------------- radix select (3-level, exact, full-chip grids) ----------------
__global__ __launch_bounds__(256) void hist_kernel(int level)
{
    const int tid = blockIdx.x * 256 + threadIdx.x;
    const bool active = tid < 2 * NANCH;
    int b = 0; unsigned long long key = 0;
    if (active) {
        b = tid / NANCH;
        key = g_keys[b * NANCH + (tid - b * NANCH)];
    }
    const int b1 = (int)(key >> 48);
    const int b2 = (int)((key >> 32) & 0xFFFF);
    const int b3 = (int)(key & 0xFFFF);

    if (level == 0) {
        const unsigned act = __ballot_sync(0xffffffffu, active);
        if (active) {
            const int tag = (b << 16) | b1;
            const unsigned mm = __match_any_sync(act, tag);
            const int leader = __ffs(mm) - 1;
            if ((threadIdx.x & 31) == leader)
                atomicAdd(&g_hist[0][b][b1], __popc(mm));
        }
    } else if (level == 1) {
        if (active && b1 == g_T[0][b]) atomicAdd(&g_hist[1][b][b2], 1);
    } else {
        if (active && b1 == g_T[0][b] && b2 == g_T[1][b]) atomicAdd(&g_hist[2][b][b3], 1);
    }
}

__global__ __launch_bounds__(1024) void scan_kernel(int level)
{
    const int b = blockIdx.x;
    const int s = threadIdx.x;
    const int* hist = g_hist[level][b];

    __shared__ int a[1024];

    int sum = 0;
    const int4* h4 = (const int4*)(hist + s * 64);
#pragma unroll
    for (int q = 0; q < 16; q++) { int4 v = h4[q]; sum += v.x + v.y + v.z + v.w; }
    a[s] = sum;
    __syncthreads();
    for (int off = 1; off < 1024; off <<= 1) {
        const int v = (s + off < 1024) ? a[s + off] : 0;
        __syncthreads();
        a[s] += v;
        __syncthreads();
    }

    int budget = NPRE;
    if (level >= 1) budget -= g_G[0][b];
    if (level >= 2) budget -= g_G[1][b];

    const int nxt = (s < 1023) ? a[s + 1] : 0;
    if (a[s] >= budget && nxt < budget) {
        int vals[64];
#pragma unroll
        for (int q = 0; q < 16; q++) {
            int4 v = h4[q];
            vals[q * 4] = v.x; vals[q * 4 + 1] = v.y; vals[q * 4 + 2] = v.z; vals[q * 4 + 3] = v.w;
        }
        int run = nxt, T = -1, G = 0;
#pragma unroll
        for (int v = 63; v >= 0; v--) {
            run += vals[v];
            if (run >= budget) { T = s * 64 + v; G = run - vals[v]; break; }
        }
        g_T[level][b] = T; g_G[level][b] = G;
    }
}

__global__ __launch_bounds__(256) void compact_kernel()
{
    const int tid = blockIdx.x * 256 + threadIdx.x;
    if (tid >= 2 * NANCH) return;
    const int b = tid / NANCH;
    const unsigned long long key = g_keys[b * NANCH + (tid - b * NANCH)];
    const int b1 = (int)(key >> 48);
    const int b2 = (int)((key >> 32) & 0xFFFF);
    const int b3 = (int)(key & 0xFFFF);
    const int T1 = g_T[0][b], T2 = g_T[1][b], T3 = g_T[2][b];
    const bool keep = (b1 > T1) ||
                      (b1 == T1 && (b2 > T2 || (b2 == T2 && b3 >= T3)));
    if (keep) {
        const int slot = atomicAdd(&g_cnt[b], 1);
        g_cand[b][slot] = key;
    }
}

// ---------------- sort 6000 (pad 8192) + gather ----------------
__global__ __launch_bounds__(1024) void sort_gather2()
{
    extern __shared__ unsigned long long sk[];
    const int b = blockIdx.x;
    const int t = threadIdx.x;

    for (int i = t; i < NSORT2; i += 1024)
        sk[i] = (i < NPRE) ? g_cand[b][i] : 0ull;
    __syncthreads();

    for (int k = 2; k <= NSORT2; k <<= 1) {
        for (int j = k >> 1; j > 0; j >>= 1) {
#pragma unroll
            for (int s = 0; s < 4; s++) {
                const int c = t + s * 1024;
                const int i = ((c & ~(j - 1)) << 1) | (c & (j - 1));
                const int p = i + j;
                const bool desc = ((i & k) == 0);
                const unsigned long long x = sk[i], y = sk[p];
                const bool sw = desc ? (x < y) : (x > y);
                if (sw) { sk[i] = y; sk[p] = x; }
            }
            __syncthreads();
        }
    }

    for (int r = t; r < NPRE; r += 1024) {
        const unsigned long long key = sk[r];
        const unsigned idx = 0xFFFFFFFFu - (unsigned)(key & 0xFFFFFFFFull);
        const float4 v = *(const float4*)&g_boxes[((size_t)(b * NANCH + idx)) * 4];
        *(float4*)&g_boxes6k[((size_t)(b * NPRE + r)) * 4] = v;
        g_scores6k[b * NPRE + r] = g_scores[b * NANCH + idx];
    }
}

// ---------------- fused NMS + selection + output (lazy IoU, boxes in smem) ----------------
__global__ __launch_bounds__(512) void nms_select_kernel(float* __restrict__ out)
{
    extern __shared__ __align__(16) float4 sbox[];       // 6000 float4 = 96KB
    __shared__ unsigned long long live[NWORDS];
    __shared__ int keep[NPOST];
    __shared__ int s_pick, s_count, s_done, s_nvalid;

    const int b = blockIdx.x;
    const int t = threadIdx.x;

    for (int i = t; i < NPRE; i += 512)
        sbox[i] = *(const float4*)&g_boxes6k[((size_t)(b * NPRE + i)) * 4];

    if (t < NWORDS) live[t] = (t == NWORDS - 1) ? ((1ull << 48) - 1ull) : ~0ull;
    if (t == 0) { s_count = 0; s_done = 0; s_nvalid = NPRE; }
    __syncthreads();

    for (int i = t; i < NPRE; i += 512) {
        if (g_scores6k[b * NPRE + i] < 0.f) atomicMin(&s_nvalid, i);
    }
    __syncthreads();
    const int nvalid = s_nvalid;

    while (true) {
        if (t == 0) {
            int nxt = -1;
            for (int w = 0; w < NWORDS; w++) {
                const unsigned long long v = live[w];
                if (v) { nxt = w * 64 + (__ffsll((long long)v) - 1); break; }
            }
            if (nxt < 0 || nxt >= nvalid || s_count >= NPOST) {
                s_done = 1;
            } else {
                s_pick = nxt;
                keep[s_count] = nxt;
                s_count++;
                live[nxt >> 6] &= ~(1ull << (nxt & 63));
            }
        }
        __syncthreads();
        if (s_done) break;
        const int i = s_pick;
        const float4 bi = sbox[i];
        const float ai = (bi.z - bi.x) * (bi.w - bi.y);
        for (int j = i + 1 + t; j < NPRE; j += 512) {
            if ((live[j >> 6] >> (j & 63)) & 1ull) {
                const float4 bj = sbox[j];
                const float ix1 = fmaxf(bi.x, bj.x), iy1 = fmaxf(bi.y, bj.y);
                const float ix2 = fminf(bi.z, bj.z), iy2 = fminf(bi.w, bj.w);
                const float inter = fmaxf(ix2 - ix1, 0.f) * fmaxf(iy2 - iy1, 0.f);
                const float aj = (bj.z - bj.x) * (bj.w - bj.y);
                const float iou = inter / (ai + aj - inter);
                if (iou > NMS_T)
                    atomicAnd(&live[j >> 6], ~(1ull << (j & 63)));
            }
        }
        __syncthreads();
    }

    const int cnt = s_count;
    for (int r = t; r < NPOST; r += 512) {
        float bx0 = 0.f, bx1 = 0.f, bx2 = 0.f, bx3 = 0.f, sv = 0.f, mv = 0.f;
        if (r < cnt) {
            const int i = keep[r];
            const float4 bp = sbox[i];
            bx0 = bp.x; bx1 = bp.y; bx2 = bp.z; bx3 = bp.w;
            sv = g_scores6k[b * NPRE + i];
            mv = 1.f;
        }
        float* ob = out + b * (NPOST * 4) + r * 4;
        ob[0] = bx0; ob[1] = bx1; ob[2] = bx2; ob[3] = bx3;
        out[2 * NPOST * 4 + b * NPOST + r] = sv;
        out[2 * NPOST * 4 + 2 * NPOST + b * NPOST + r] = mv;
    }
}

// ---------------- launch ----------------
extern "C" void kernel_launch(void* const* d_in, const int* in_sizes, int n_in,
                              void* d_out, int out_size)
{
    const float* x   = (const float*)d_in[0];
    const float* c1w = (const float*)d_in[1];
    const float* c1b = (const float*)d_in[2];
    const float* ow  = (const float*)d_in[3];
    const float* ob  = (const float*)d_in[4];
    const float* lw  = (const float*)d_in[5];
    const float* lb  = (const float*)d_in[6];
    const float* anc = (const float*)d_in[7];
    const int*   ih  = (const int*)d_in[8];
    const int*   iw  = (const int*)d_in[9];
    float* out = (float*)d_out;

    cudaFuncSetAttribute(conv_mma_kernel,
                         cudaFuncAttributeMaxDynamicSharedMemorySize, SMEM_CONV);
    cudaFuncSetAttribute(sort_gather2,
                         cudaFuncAttributeMaxDynamicSharedMemorySize,
                         NSORT2 * (int)sizeof(unsigned long long));
    cudaFuncSetAttribute(nms_select_kernel,
                         cudaFuncAttributeMaxDynamicSharedMemorySize,
                         NPRE * (int)sizeof(float4));

    zero_kernel<<<(3 * 2 * 65536 + 1023) / 1024, 1024>>>();
    split_w_kernel<<<(CMID * KDIM + 255) / 256, 256>>>(c1w);
    split_x_kernel<<<(2 * PPOS * 256 + 255) / 256, 256>>>(x);
    conv_mma_kernel<<<dim3(40, 8, 2), 256, SMEM_CONV>>>(c1b);
    heads_kernel<<<dim3(157, 2), 256>>>(ow, ob, lw, lb, anc, ih, iw);

    const int ng = (2 * NANCH + 255) / 256;
    hist_kernel<<<ng, 256>>>(0);
    scan_kernel<<<2, 1024>>>(0);
    hist_kernel<<<ng, 256>>>(1);
    scan_kernel<<<2, 1024>>>(1);
    hist_kernel<<<ng, 256>>>(2);
    scan_kernel<<<2, 1024>>>(2);
    compact_kernel<<<ng, 256>>>();

    sort_gather2<<<2, 1024, NSORT2 * sizeof(unsigned long long)>>>();
    nms_select_kernel<<<2, 512, NPRE * sizeof(float4)>>>(out);
}

// round 16
// speedup vs baseline: 2.7322x; 2.7322x over previous
#include <cuda_runtime.h>
#include <cuda_bf16.h>
#include <math.h>
#include <stdint.h>

#define FH 50
#define FW 50
#define NPOS 2500
#define CIN 256
#define CMID 512
#define KDIM 2304          // 256*9 (reordered: (ky*3+kx)*256+ci)
#define APER 9
#define NANCH 22500
#define NPRE 6000
#define NPOST 300
#define NSORT2 8192
#define NWORDS 94
#define NMS_T 0.7f
#define MINSZ 16.0f

#define BM 64
#define BN 64
#define NKT 36             // 36 k-tiles of 64: (ky,kx) = kt/4, ci0 = (kt%4)*64
#define PPOS 2704          // 52*52 padded positions
#define PTOT 2832          // + zero tail region

#define LOOKAHEAD 16

// smem layout (conv): DOUBLE-BUFFERED: per buf 3 A tiles (8KB) + 3 B tiles (8KB) = 48KB
#define BUFSZ    49152
#define OFF_B    (3*8192)
#define SMEM_CONV (2*BUFSZ)          // 98304

// ---------------- device scratch (zero-initialized at module load) ----------------
__device__ __align__(16) __nv_bfloat16 g_wh[CMID * KDIM];
__device__ __align__(16) __nv_bfloat16 g_wm[CMID * KDIM];
__device__ __align__(16) __nv_bfloat16 g_wl[CMID * KDIM];
__device__ __align__(16) __nv_bfloat16 g_xh[2 * PTOT * 256];
__device__ __align__(16) __nv_bfloat16 g_xm[2 * PTOT * 256];
__device__ __align__(16) __nv_bfloat16 g_xl[2 * PTOT * 256];
__device__ float g_h[2 * CMID * NPOS];
__device__ __align__(16) float g_boxes[2 * NANCH * 4];
__device__ float g_scores[2 * NANCH];
__device__ unsigned long long g_keys[2 * NANCH];
__device__ int g_hist[3][2][65536];
__device__ int g_T[3][2];
__device__ int g_G[3][2];
__device__ int g_cnt[2];
__device__ unsigned long long g_cand[2][NPRE];
__device__ __align__(16) float g_boxes6k[2 * NPRE * 4];
__device__ float g_scores6k[2 * NPRE];
__device__ unsigned long long g_mask[(size_t)2 * NPRE * NWORDS];

// ---------------- helpers ----------------
__device__ __forceinline__ uint32_t smem_u32(const void* p) {
    uint32_t a;
    asm("{ .reg .u64 t; cvta.to.shared.u64 t, %1; cvt.u32.u64 %0, t; }" : "=r"(a) : "l"(p));
    return a;
}
__device__ __forceinline__ void cp16(uint32_t saddr, const void* gptr) {
    asm volatile("cp.async.cg.shared.global [%0], [%1], 16;" :: "r"(saddr), "l"(gptr));
}
__device__ __forceinline__ void ldsm_x4(uint32_t& r0, uint32_t& r1, uint32_t& r2, uint32_t& r3,
                                        uint32_t addr) {
    asm volatile("ldmatrix.sync.aligned.m8n8.x4.shared.b16 {%0,%1,%2,%3}, [%4];"
                 : "=r"(r0), "=r"(r1), "=r"(r2), "=r"(r3) : "r"(addr));
}
__device__ __forceinline__ void mma16816(float* d, const uint32_t* a, uint32_t b0, uint32_t b1) {
    asm volatile(
        "mma.sync.aligned.m16n8k16.row.col.f32.bf16.bf16.f32 "
        "{%0,%1,%2,%3}, {%4,%5,%6,%7}, {%8,%9}, {%0,%1,%2,%3};"
        : "+f"(d[0]), "+f"(d[1]), "+f"(d[2]), "+f"(d[3])
        : "r"(a[0]), "r"(a[1]), "r"(a[2]), "r"(a[3]), "r"(b0), "r"(b1));
}
__device__ __forceinline__ void mma16816_z(float* d, const uint32_t* a, uint32_t b0, uint32_t b1) {
    asm volatile(
        "mma.sync.aligned.m16n8k16.row.col.f32.bf16.bf16.f32 "
        "{%0,%1,%2,%3}, {%4,%5,%6,%7}, {%8,%9}, {%10,%11,%12,%13};"
        : "=f"(d[0]), "=f"(d[1]), "=f"(d[2]), "=f"(d[3])
        : "r"(a[0]), "r"(a[1]), "r"(a[2]), "r"(a[3]), "r"(b0), "r"(b1),
          "f"(0.f), "f"(0.f), "f"(0.f), "f"(0.f));
}

// ---------------- zero hist/counters ----------------
__global__ __launch_bounds__(1024) void zero_kernel() {
    const int idx = blockIdx.x * 1024 + threadIdx.x;
    if (idx < 3 * 2 * 65536) ((int*)g_hist)[idx] = 0;
    if (idx < 2) g_cnt[idx] = 0;
}

// ---------------- split + reorder weights: k' = (ky*3+kx)*256 + ci ----------------
__global__ __launch_bounds__(256) void split_w_kernel(const float* __restrict__ w) {
    const int idx = blockIdx.x * 256 + threadIdx.x;
    if (idx >= CMID * KDIM) return;
    const int co = idx / KDIM;
    const int k  = idx - co * KDIM;
    const int ci = k / 9;
    const int rr = k - ci * 9;
    const int dst = co * KDIM + rr * 256 + ci;
    const float v = w[idx];
    const __nv_bfloat16 h = __float2bfloat16(v);
    const float fh = __bfloat162float(h);
    const __nv_bfloat16 m = __float2bfloat16(v - fh);
    const float fm = __bfloat162float(m);
    const __nv_bfloat16 l = __float2bfloat16(v - fh - fm);
    g_wh[dst] = h; g_wm[dst] = m; g_wl[dst] = l;
}

// ---------------- split x into channel-last padded bf16 hi/mid/lo ----------------
__global__ __launch_bounds__(256) void split_x_kernel(const float* __restrict__ x) {
    const int idx = blockIdx.x * 256 + threadIdx.x;
    if (idx >= 2 * PPOS * 256) return;
    const int b   = idx / (PPOS * 256);
    const int rem = idx - b * (PPOS * 256);
    const int pos = rem >> 8;
    const int ci  = rem & 255;
    const int py = pos / 52, px = pos - py * 52;
    const int iy = py - 1,  ix = px - 1;
    float v = 0.f;
    if (iy >= 0 && iy < FH && ix >= 0 && ix < FW)
        v = x[(((size_t)b * CIN + ci) * FH + iy) * FW + ix];
    const __nv_bfloat16 h = __float2bfloat16(v);
    const float fh = __bfloat162float(h);
    const __nv_bfloat16 m = __float2bfloat16(v - fh);
    const float fm = __bfloat162float(m);
    const __nv_bfloat16 l = __float2bfloat16(v - fh - fm);
    const size_t dst = ((size_t)b * PTOT + pos) * 256 + ci;
    g_xh[dst] = h; g_xm[dst] = m; g_xl[dst] = l;
}

// ---------------- conv 3x3 via mma.sync bf16 (R14-proven) ----------------
__global__ __launch_bounds__(256) void conv_mma_kernel(const float* __restrict__ bias) {
    extern __shared__ __align__(128) char smem[];
    const uint32_t sbase = smem_u32(smem);
    const int t    = threadIdx.x;
    const int wid  = t >> 5, lane = t & 31;
    const int wm   = wid & 1;
    const int wn   = wid >> 1;
    const int n0   = blockIdx.x * BN;
    const int co0  = blockIdx.y * BM;
    const int b    = blockIdx.z;

    const __nv_bfloat16* Asrc[3] = {g_wh, g_wm, g_wl};
    const __nv_bfloat16* Xsrc[3] = {g_xh, g_xm, g_xl};

    float acc[2][2][4];
#pragma unroll
    for (int i = 0; i < 2; i++)
#pragma unroll
        for (int j = 0; j < 2; j++)
#pragma unroll
            for (int q = 0; q < 4; q++) acc[i][j][q] = 0.f;

    const int arow_l  = lane & 15;
    const int ahalf   = lane >> 4;
    const int bq = lane >> 3, br = lane & 7;
    const int brow_l = wn * 16 + (bq >> 1) * 8 + br;
    const int bhalf  = bq & 1;

    auto stage = [&](int kt, int buf) {
        const int k0 = kt * 64;
        const int r   = kt >> 2;
        const int ky  = r / 3, kx = r - ky * 3;
        const int ci0 = (kt & 3) * 64;
        const int kofs = ky * 52 + kx;
        const uint32_t base = sbase + buf * BUFSZ;
#pragma unroll
        for (int s = 0; s < 6; s++) {
            const int i = t + s * 256;
            const int tile = i / 512, g = i - tile * 512;
            const int row = g >> 3, c = g & 7;
            const uint32_t saddr = base + tile * 8192 + row * 128 + ((c * 16) ^ ((row & 7) << 4));
            cp16(saddr, Asrc[tile] + (size_t)(co0 + row) * KDIM + k0 + c * 8);
        }
#pragma unroll
        for (int s = 0; s < 6; s++) {
            const int i = t + s * 256;
            const int tile = i / 512, g = i - tile * 512;
            const int row = g >> 3, c = g & 7;
            const int n = n0 + row;
            int pos;
            if (n < NPOS) { const int y = n / FW; pos = y * 52 + (n - y * FW) + kofs; }
            else pos = PPOS;
            const uint32_t saddr = base + OFF_B + tile * 8192 + row * 128 + ((c * 16) ^ ((row & 7) << 4));
            cp16(saddr, Xsrc[tile] + ((size_t)b * PTOT + pos) * 256 + ci0 + c * 8);
        }
        asm volatile("cp.async.commit_group;" ::: "memory");
    };

    stage(0, 0);
    asm volatile("cp.async.wait_group 0;" ::: "memory");
    __syncthreads();

    for (int kt = 0; kt < NKT; kt++) {
        const int p = kt & 1;
        const bool more = (kt + 1) < NKT;
        if (more) stage(kt + 1, 1 - p);

        const uint32_t base = sbase + p * BUFSZ;
#pragma unroll
        for (int ks = 0; ks < 4; ks++) {
            uint32_t afr[3][2][4];
            uint32_t bfr[3][4];
#pragma unroll
            for (int tile = 0; tile < 3; tile++) {
#pragma unroll
                for (int mf = 0; mf < 2; mf++) {
                    const int row = wm * 32 + mf * 16 + arow_l;
                    const int cb  = ks * 32 + ahalf * 16;
                    const uint32_t addr = base + tile * 8192 + row * 128 +
                                          (cb ^ ((row & 7) << 4));
                    ldsm_x4(afr[tile][mf][0], afr[tile][mf][1], afr[tile][mf][2], afr[tile][mf][3], addr);
                }
                {
                    const int cb = ks * 32 + bhalf * 16;
                    const uint32_t addr = base + OFF_B + tile * 8192 + brow_l * 128 +
                                          (cb ^ ((brow_l & 7) << 4));
                    ldsm_x4(bfr[tile][0], bfr[tile][1], bfr[tile][2], bfr[tile][3], addr);
                }
            }
#pragma unroll
            for (int mf = 0; mf < 2; mf++) {
#pragma unroll
                for (int nf = 0; nf < 2; nf++) {
                    const uint32_t b0h = bfr[0][nf * 2], b1h = bfr[0][nf * 2 + 1];
                    const uint32_t b0m = bfr[1][nf * 2], b1m = bfr[1][nf * 2 + 1];
                    const uint32_t b0l = bfr[2][nf * 2], b1l = bfr[2][nf * 2 + 1];
                    float tmp[4];
                    mma16816_z(tmp, afr[0][mf], b0h, b1h);   // hh
                    mma16816 (tmp, afr[0][mf], b0m, b1m);    // hm
                    mma16816 (tmp, afr[1][mf], b0h, b1h);    // mh
                    mma16816 (tmp, afr[0][mf], b0l, b1l);    // hl
                    mma16816 (tmp, afr[2][mf], b0h, b1h);    // lh
                    mma16816 (tmp, afr[1][mf], b0m, b1m);    // mm
#pragma unroll
                    for (int q = 0; q < 4; q++) acc[mf][nf][q] += tmp[q];
                }
            }
        }
        if (more) {
            asm volatile("cp.async.wait_group 0;" ::: "memory");
            __syncthreads();
        }
    }

#pragma unroll
    for (int mf = 0; mf < 2; mf++) {
#pragma unroll
        for (int nf = 0; nf < 2; nf++) {
#pragma unroll
            for (int q = 0; q < 4; q++) {
                const int co = co0 + wm * 32 + mf * 16 + (lane >> 2) + (q >= 2 ? 8 : 0);
                const int n  = n0 + wn * 16 + nf * 8 + (lane & 3) * 2 + (q & 1);
                if (n < NPOS) {
                    float v = acc[mf][nf][q] + bias[co];
                    g_h[((size_t)(b * CMID + co)) * NPOS + n] = v > 0.f ? v : 0.f;
                }
            }
        }
    }
}

// ---------------- heads (R1-proven) ----------------
__device__ __forceinline__ float to_dim(const int* p) {
    int v = *p;
    if (v > 0 && v < 100000) return (float)v;
    return __int_as_float(v);
}

__global__ __launch_bounds__(256) void heads_kernel(
    const float* __restrict__ ow, const float* __restrict__ ob,
    const float* __restrict__ lw, const float* __restrict__ lb,
    const float* __restrict__ anchors, const int* ihp, const int* iwp)
{
    const int b  = blockIdx.y;
    const int n0 = blockIdx.x * 16;
    const int t  = threadIdx.x;

    __shared__ float hs[CMID][17];
    __shared__ float outs[54][16];

    for (int idx = t; idx < CMID * 16; idx += 256) {
        const int c = idx >> 4, i = idx & 15;
        const int n = n0 + i;
        hs[c][i] = (n < NPOS) ? g_h[((size_t)(b * CMID + c)) * NPOS + n] : 0.f;
    }
    __syncthreads();

    {
        const int i = t & 15, g = t >> 4;
        float acc[4] = {0.f, 0.f, 0.f, 0.f};
        const float* wp[4];
        float bs[4];
#pragma unroll
        for (int s = 0; s < 4; s++) {
            const int oc = g + s * 16;
            if (oc < 18)       { wp[s] = ow + oc * CMID;        bs[s] = ob[oc]; }
            else if (oc < 54)  { wp[s] = lw + (oc - 18) * CMID; bs[s] = lb[oc - 18]; }
            else               { wp[s] = ow;                    bs[s] = 0.f; }
        }
#pragma unroll 4
        for (int c = 0; c < CMID; c++) {
            const float v = hs[c][i];
            acc[0] += wp[0][c] * v;
            acc[1] += wp[1][c] * v;
            acc[2] += wp[2][c] * v;
            acc[3] += wp[3][c] * v;
        }
#pragma unroll
        for (int s = 0; s < 4; s++) {
            const int oc = g + s * 16;
            if (oc < 54) outs[oc][i] = acc[s] + bs[s];
        }
    }
    __syncthreads();

    if (t < 144) {
        const int i = t & 15, a = t >> 4;
        const int n = n0 + i;
        if (n < NPOS) {
            const float imgw = to_dim(iwp), imgh = to_dim(ihp);
            const int m = n * APER + a;
            const float o0 = outs[2 * a][i], o1 = outs[2 * a + 1][i];
            const float mx = fmaxf(o0, o1);
            const float e0 = expf(o0 - mx), e1 = expf(o1 - mx);
            const float sc = e1 / (e0 + e1);

            const float l0 = outs[18 + 4 * a + 0][i];
            const float l1 = outs[18 + 4 * a + 1][i];
            const float l2 = outs[18 + 4 * a + 2][i];
            const float l3 = outs[18 + 4 * a + 3][i];

            const float a0 = anchors[m * 4 + 0], a1 = anchors[m * 4 + 1];
            const float a2 = anchors[m * 4 + 2], a3 = anchors[m * 4 + 3];
            const float aw = a2 - a0, ah = a3 - a1;
            const float acx = a0 + 0.5f * aw, acy = a1 + 0.5f * ah;
            const float cx = acx + l0 * aw, cy = acy + l1 * ah;
            const float wd = aw * expf(l2), hh = ah * expf(l3);
            float x1 = fminf(fmaxf(cx - 0.5f * wd, 0.f), imgw);
            float y1 = fminf(fmaxf(cy - 0.5f * hh, 0.f), imgh);
            float x2 = fminf(fmaxf(cx + 0.5f * wd, 0.f), imgw);
            float y2 = fminf(fmaxf(cy + 0.5f * hh, 0.f), imgh);

            const bool valid = (x2 - x1 >= MINSZ) && (y2 - y1 >= MINSZ);
            const float s2 = valid ? sc : -1.f;

            float* bp = g_boxes + ((size_t)(b * NANCH + m)) * 4;
            bp[0] = x1; bp[1] = y1; bp[2] = x2; bp[3] = y2;
            g_scores[b * NANCH + m] = s2;

            const unsigned sb = __float_as_uint(s2);
            const unsigned mono = (sb & 0x80000000u) ? ~sb : (sb | 0x80000000u);
            g_keys[b * NANCH + m] =
                ((unsigned long long)mono << 32) |
                (unsigned long long)(0xFFFFFFFFu - (unsigned)m);
        }
    }
}

// ---------------- radix select (3-level, exact, full-chip grids) ----------------
__global__ __launch_bounds__(256) void hist_kernel(int level)
{
    const int tid = blockIdx.x * 256 + threadIdx.x;
    const bool active = tid < 2 * NANCH;
    int b = 0; unsigned long long key = 0;
    if (active) {
        b = tid / NANCH;
        key = g_keys[b * NANCH + (tid - b * NANCH)];
    }
    const int b1 = (int)(key >> 48);
    const int b2 = (int)((key >> 32) & 0xFFFF);
    const int b3 = (int)(key & 0xFFFF);

    if (level == 0) {
        const unsigned act = __ballot_sync(0xffffffffu, active);
        if (active) {
            const int tag = (b << 16) | b1;
            const unsigned mm = __match_any_sync(act, tag);
            const int leader = __ffs(mm) - 1;
            if ((threadIdx.x & 31) == leader)
                atomicAdd(&g_hist[0][b][b1], __popc(mm));
        }
    } else if (level == 1) {
        if (active && b1 == g_T[0][b]) atomicAdd(&g_hist[1][b][b2], 1);
    } else {
        if (active && b1 == g_T[0][b] && b2 == g_T[1][b]) atomicAdd(&g_hist[2][b][b3], 1);
    }
}

__global__ __launch_bounds__(1024) void scan_kernel(int level)
{
    const int b = blockIdx.x;
    const int s = threadIdx.x;
    const int* hist = g_hist[level][b];

    __shared__ int a[1024];

    int sum = 0;
    const int4* h4 = (const int4*)(hist + s * 64);
#pragma unroll
    for (int q = 0; q < 16; q++) { int4 v = h4[q]; sum += v.x + v.y + v.z + v.w; }
    a[s] = sum;
    __syncthreads();
    for (int off = 1; off < 1024; off <<= 1) {
        const int v = (s + off < 1024) ? a[s + off] : 0;
        __syncthreads();
        a[s] += v;
        __syncthreads();
    }

    int budget = NPRE;
    if (level >= 1) budget -= g_G[0][b];
    if (level >= 2) budget -= g_G[1][b];

    const int nxt = (s < 1023) ? a[s + 1] : 0;
    if (a[s] >= budget && nxt < budget) {
        int vals[64];
#pragma unroll
        for (int q = 0; q < 16; q++) {
            int4 v = h4[q];
            vals[q * 4] = v.x; vals[q * 4 + 1] = v.y; vals[q * 4 + 2] = v.z; vals[q * 4 + 3] = v.w;
        }
        int run = nxt, T = -1, G = 0;
#pragma unroll
        for (int v = 63; v >= 0; v--) {
            run += vals[v];
            if (run >= budget) { T = s * 64 + v; G = run - vals[v]; break; }
        }
        g_T[level][b] = T; g_G[level][b] = G;
    }
}

__global__ __launch_bounds__(256) void compact_kernel()
{
    const int tid = blockIdx.x * 256 + threadIdx.x;
    if (tid >= 2 * NANCH) return;
    const int b = tid / NANCH;
    const unsigned long long key = g_keys[b * NANCH + (tid - b * NANCH)];
    const int b1 = (int)(key >> 48);
    const int b2 = (int)((key >> 32) & 0xFFFF);
    const int b3 = (int)(key & 0xFFFF);
    const int T1 = g_T[0][b], T2 = g_T[1][b], T3 = g_T[2][b];
    const bool keep = (b1 > T1) ||
                      (b1 == T1 && (b2 > T2 || (b2 == T2 && b3 >= T3)));
    if (keep) {
        const int slot = atomicAdd(&g_cnt[b], 1);
        g_cand[b][slot] = key;
    }
}

// ---------------- sort 6000 (pad 8192) + gather ----------------
__global__ __launch_bounds__(1024) void sort_gather2()
{
    extern __shared__ unsigned long long sk[];
    const int b = blockIdx.x;
    const int t = threadIdx.x;

    for (int i = t; i < NSORT2; i += 1024)
        sk[i] = (i < NPRE) ? g_cand[b][i] : 0ull;
    __syncthreads();

    for (int k = 2; k <= NSORT2; k <<= 1) {
        for (int j = k >> 1; j > 0; j >>= 1) {
#pragma unroll
            for (int s = 0; s < 4; s++) {
                const int c = t + s * 1024;
                const int i = ((c & ~(j - 1)) << 1) | (c & (j - 1));
                const int p = i + j;
                const bool desc = ((i & k) == 0);
                const unsigned long long x = sk[i], y = sk[p];
                const bool sw = desc ? (x < y) : (x > y);
                if (sw) { sk[i] = y; sk[p] = x; }
            }
            __syncthreads();
        }
    }

    for (int r = t; r < NPRE; r += 1024) {
        const unsigned long long key = sk[r];
        const unsigned idx = 0xFFFFFFFFu - (unsigned)(key & 0xFFFFFFFFull);
        const float4 v = *(const float4*)&g_boxes[((size_t)(b * NANCH + idx)) * 4];
        *(float4*)&g_boxes6k[((size_t)(b * NPRE + r)) * 4] = v;
        g_scores6k[b * NPRE + r] = g_scores[b * NANCH + idx];
    }
}

// ---------------- NMS masks ----------------
__global__ __launch_bounds__(64) void nms_mask_kernel() {
    const int cb = blockIdx.x, rb = blockIdx.y, b = blockIdx.z;
    if (cb < rb) return;
    __shared__ float4 cbox[64];
    __shared__ float carea[64];
    const int t = threadIdx.x;
    const int j0 = cb * 64 + t;
    if (j0 < NPRE) {
        float4 v = *(const float4*)&g_boxes6k[((size_t)(b * NPRE + j0)) * 4];
        cbox[t] = v;
        carea[t] = (v.z - v.x) * (v.w - v.y);
    }
    __syncthreads();
    const int i = rb * 64 + t;
    if (i >= NPRE) return;
    const float4 bi = *(const float4*)&g_boxes6k[((size_t)(b * NPRE + i)) * 4];
    const float ai = (bi.z - bi.x) * (bi.w - bi.y);
    unsigned long long bits = 0ull;
    const int jmax = min(64, NPRE - cb * 64);
    for (int jj = 0; jj < jmax; jj++) {
        const int jg = cb * 64 + jj;
        if (jg <= i) continue;
        const float4 bj = cbox[jj];
        const float ix1 = fmaxf(bi.x, bj.x), iy1 = fmaxf(bi.y, bj.y);
        const float ix2 = fminf(bi.z, bj.z), iy2 = fminf(bi.w, bj.w);
        const float inter = fmaxf(ix2 - ix1, 0.f) * fmaxf(iy2 - iy1, 0.f);
        const float iou = inter / (ai + carea[jj] - inter);
        if (iou > NMS_T) bits |= 1ull << jj;
    }
    g_mask[((size_t)(b * NPRE + i)) * NWORDS + cb] = bits;
}

// ---------------- selection: batched 16-candidate lookahead ----------------
__global__ __launch_bounds__(256) void select_out_kernel(float* __restrict__ out) {
    const int b = blockIdx.x;
    const int t = threadIdx.x;
    __shared__ unsigned long long removed[NWORDS];
    __shared__ unsigned long long rows[LOOKAHEAD][NWORDS];
    __shared__ int cand[LOOKAHEAD];
    __shared__ int keep[NPOST];
    __shared__ int s_k, s_count, s_done, s_nvalid, s_pick;

    for (int w = t; w < NWORDS; w += 256) removed[w] = 0ull;
    if (t == 0) { s_count = 0; s_done = 0; s_nvalid = NPRE; }
    __syncthreads();

    for (int i = t; i < NPRE; i += 256) {
        if (g_scores6k[b * NPRE + i] < 0.f) atomicMin(&s_nvalid, i);
    }
    __syncthreads();

    while (true) {
        if (t == 0) {
            const int nvalid = s_nvalid;
            int k = 0;
            bool fin = false;
            for (int w = 0; w < NWORDS && k < LOOKAHEAD && !fin; w++) {
                unsigned long long v = ~removed[w];
                if (w == NWORDS - 1) v &= ((1ull << (NPRE - 64 * (NWORDS - 1))) - 1ull);
                while (v && k < LOOKAHEAD) {
                    const int bpos = __ffsll((long long)v) - 1;
                    const int idx = w * 64 + bpos;
                    if (idx >= nvalid) { fin = true; break; }
                    cand[k++] = idx;
                    v &= v - 1;
                }
            }
            s_k = k;
            if (k == 0) s_done = 1;
        }
        __syncthreads();
        if (s_done) break;
        const int k = s_k;

        for (int i = t; i < k * NWORDS; i += 256) {
            const int r = i / NWORDS, w = i - r * NWORDS;
            rows[r][w] = g_mask[((size_t)(b * NPRE + cand[r])) * NWORDS + w];
        }
        __syncthreads();

        for (int r = 0; r < k; r++) {
            if (t == 0) {
                const int idx = cand[r];
                const bool live = !((removed[idx >> 6] >> (idx & 63)) & 1ull);
                if (live && s_count < NPOST) {
                    keep[s_count] = idx;
                    s_count++;
                    removed[idx >> 6] |= 1ull << (idx & 63);
                    s_pick = 1;
                    if (s_count >= NPOST) s_done = 1;
                } else {
                    s_pick = 0;
                }
            }
            __syncthreads();
            if (s_pick) {
                for (int w = t; w < NWORDS; w += 256) removed[w] |= rows[r][w];
            }
            __syncthreads();
            if (s_done) break;
        }
        if (s_done) break;
    }

    const int cnt = s_count;
    for (int r = t; r < NPOST; r += 256) {
        float bx0 = 0.f, bx1 = 0.f, bx2 = 0.f, bx3 = 0.f, sv = 0.f, mv = 0.f;
        if (r < cnt) {
            const int i = keep[r];
            const float* bp = g_boxes6k + ((size_t)(b * NPRE + i)) * 4;
            bx0 = bp[0]; bx1 = bp[1]; bx2 = bp[2]; bx3 = bp[3];
            sv = g_scores6k[b * NPRE + i];
            mv = 1.f;
        }
        float* ob = out + b * (NPOST * 4) + r * 4;
        ob[0] = bx0; ob[1] = bx1; ob[2] = bx2; ob[3] = bx3;
        out[2 * NPOST * 4 + b * NPOST + r] = sv;
        out[2 * NPOST * 4 + 2 * NPOST + b * NPOST + r] = mv;
    }
}

// ---------------- launch ----------------
extern "C" void kernel_launch(void* const* d_in, const int* in_sizes, int n_in,
                              void* d_out, int out_size)
{
    const float* x   = (const float*)d_in[0];
    const float* c1w = (const float*)d_in[1];
    const float* c1b = (const float*)d_in[2];
    const float* ow  = (const float*)d_in[3];
    const float* ob  = (const float*)d_in[4];
    const float* lw  = (const float*)d_in[5];
    const float* lb  = (const float*)d_in[6];
    const float* anc = (const float*)d_in[7];
    const int*   ih  = (const int*)d_in[8];
    const int*   iw  = (const int*)d_in[9];
    float* out = (float*)d_out;

    cudaFuncSetAttribute(conv_mma_kernel,
                         cudaFuncAttributeMaxDynamicSharedMemorySize, SMEM_CONV);
    cudaFuncSetAttribute(sort_gather2,
                         cudaFuncAttributeMaxDynamicSharedMemorySize,
                         NSORT2 * (int)sizeof(unsigned long long));

    zero_kernel<<<(3 * 2 * 65536 + 1023) / 1024, 1024>>>();
    split_w_kernel<<<(CMID * KDIM + 255) / 256, 256>>>(c1w);
    split_x_kernel<<<(2 * PPOS * 256 + 255) / 256, 256>>>(x);
    conv_mma_kernel<<<dim3(40, 8, 2), 256, SMEM_CONV>>>(c1b);
    heads_kernel<<<dim3(157, 2), 256>>>(ow, ob, lw, lb, anc, ih, iw);

    const int ng = (2 * NANCH + 255) / 256;
    hist_kernel<<<ng, 256>>>(0);
    scan_kernel<<<2, 1024>>>(0);
    hist_kernel<<<ng, 256>>>(1);
    scan_kernel<<<2, 1024>>>(1);
    hist_kernel<<<ng, 256>>>(2);
    scan_kernel<<<2, 1024>>>(2);
    compact_kernel<<<ng, 256>>>();

    sort_gather2<<<2, 1024, NSORT2 * sizeof(unsigned long long)>>>();
    nms_mask_kernel<<<dim3(NWORDS, NWORDS, 2), 64>>>();
    select_out_kernel<<<2, 256>>>(out);
}